// round 14
// baseline (speedup 1.0000x reference)
#include <cuda_runtime.h>
#include <cuda_fp16.h>
#include <cstdint>

#define B_   1024
#define T_   64
#define D_   512
#define H_   512
#define G4_  2048   // 4*H

// ---------------- device scratch (no allocation allowed) --------------------
__device__ __half2 g_xph[(size_t)T_ * B_ * (G4_/2)];   // 256 MB: x@W + bias, [t][b][n2] half2
__device__ __half2 g_xh2[(size_t)T_ * (D_/2) * B_];    // 64 MB: X, [t][k2][b]
__device__ __half2 g_wh2[(size_t)(D_/2) * G4_];        // 2 MB: W, [k2][n]
__device__ __half2 g_uh2[(size_t)(H_/2) * G4_];        // 2 MB: U, [k2][n]
__device__ __half2 g_h2[2][(size_t)(H_/2) * B_];       // 2x1 MB: h, [k2][b], ping-pong
__device__ unsigned g_prog[8][16];                     // completed-step counter per (by, bx)

// ---------------- helpers ---------------------------------------------------
__device__ __forceinline__ void mma16(float* c, const uint32_t* a, const uint32_t* b) {
    asm volatile(
        "mma.sync.aligned.m16n8k16.row.col.f32.f16.f16.f32 "
        "{%0,%1,%2,%3}, {%4,%5,%6,%7}, {%8,%9}, {%0,%1,%2,%3};\n"
        : "+f"(c[0]), "+f"(c[1]), "+f"(c[2]), "+f"(c[3])
        : "r"(a[0]), "r"(a[1]), "r"(a[2]), "r"(a[3]),
          "r"(b[0]), "r"(b[1]));
}

__device__ __forceinline__ float sigm(float x) { return 1.0f / (1.0f + __expf(-x)); }
__device__ __forceinline__ float tanh_(float x) { return 1.0f - 2.0f / (__expf(2.0f * x) + 1.0f); }

__device__ __forceinline__ uint32_t h2bits(float a, float b) {
    __half2 h = __floats2half2_rn(a, b);
    return *reinterpret_cast<uint32_t*>(&h);
}

__device__ __forceinline__ void cp16(uint32_t s, const void* g) {
    asm volatile("cp.async.cg.shared.global [%0], [%1], 16;\n" :: "r"(s), "l"(g));
}
__device__ __forceinline__ void cpcommit() { asm volatile("cp.async.commit_group;\n"); }
template<int N> __device__ __forceinline__ void cpwait() {
    asm volatile("cp.async.wait_group %0;\n" :: "n"(N));
}

// ---------------- prep kernels ----------------------------------------------
__global__ void conv_wu(const float* __restrict__ W, const float* __restrict__ U) {
    const int i = blockIdx.x * blockDim.x + threadIdx.x;  // (D/2)*G4 = 512K
    const int n = i & (G4_ - 1), k2 = i >> 11;
    g_wh2[i] = __floats2half2_rn(W[(size_t)(2 * k2) * G4_ + n], W[(size_t)(2 * k2 + 1) * G4_ + n]);
    g_uh2[i] = __floats2half2_rn(U[(size_t)(2 * k2) * G4_ + n], U[(size_t)(2 * k2 + 1) * G4_ + n]);
}

// X[b][t][k] fp32 -> g_xh2[t][k2][b] half2
__global__ void prep_xh(const float* __restrict__ X) {
    __shared__ float tile[32][33];   // [b_local][k_local]
    const int t = blockIdx.z, k0 = blockIdx.x * 32, b0 = blockIdx.y * 32;
    const int tx = threadIdx.x, ty = threadIdx.y;
#pragma unroll
    for (int i = 0; i < 4; i++)
        tile[ty + i * 8][tx] = X[((size_t)(b0 + ty + i * 8) * T_ + t) * D_ + k0 + tx];
    __syncthreads();
#pragma unroll
    for (int i = 0; i < 2; i++) {
        const int k2 = ty + i * 8;   // 0..15
        g_xh2[((size_t)t * (D_ / 2) + (k0 >> 1) + k2) * B_ + b0 + tx] =
            __floats2half2_rn(tile[tx][2 * k2], tile[tx][2 * k2 + 1]);
    }
}

__global__ void zero_state() {
    const int i = blockIdx.x * blockDim.x + threadIdx.x;   // (H/2)*B = 262144
    const __half2 z = __floats2half2_rn(0.0f, 0.0f);
    g_h2[0][i] = z;
    g_h2[1][i] = z;
    if (i < 128) ((unsigned*)g_prog)[i] = 0u;
}

// ---------------- stage 1: fp16 pipelined GEMM (frozen) ---------------------
// XP = Xperm @ W + bias (-> half2), tiles 128x128, KC=32, grid (16,512), 2 CTA/SM
__global__ void __launch_bounds__(256, 2)
gemm_x(const float* __restrict__ bias)
{
    constexpr int AROW = 136, BROW = 136;          // mod 32 == 8 -> conflict-free
    constexpr int STW  = 16 * AROW + 16 * BROW;    // 4352 words per stage

    extern __shared__ __align__(16) uint32_t sm[];
    const uint32_t sbase = (uint32_t)__cvta_generic_to_shared(sm);

    const int tid = threadIdx.x;
    const int bx = blockIdx.x, by = blockIdx.y;

    const int tt = by >> 3, m0 = (by & 7) * 128;
    const __half2* Ab = g_xh2 + (size_t)tt * (D_ / 2) * B_ + m0;

    uint32_t offA[2], offB[2];
    const __half2* aG[2];
    const __half2* bG[2];
#pragma unroll
    for (int c = 0; c < 2; c++) {
        const int q = tid + c * 256;
        const int k2 = q >> 5, m4 = (q & 31) * 4;
        offA[c] = (uint32_t)(k2 * AROW + m4);
        aG[c]   = Ab + (size_t)k2 * B_ + m4;
        offB[c] = (uint32_t)(16 * AROW + k2 * BROW + m4);
        bG[c]   = g_wh2 + (size_t)k2 * G4_ + bx * 128 + m4;
    }

    const int warp = tid >> 5, lane = tid & 31;
    const int wm = warp >> 2, wn = warp & 3;
    const int gq = lane >> 2, tq = lane & 3;

    float acc[4][4][4] = {};

    auto ISSUE = [&](int kt, int s) {
#pragma unroll
        for (int c = 0; c < 2; c++) {
            cp16(sbase + (uint32_t)(s * STW + offA[c]) * 4u, aG[c] + (size_t)kt * 16 * B_);
            cp16(sbase + (uint32_t)(s * STW + offB[c]) * 4u, bG[c] + (size_t)kt * 16 * G4_);
        }
    };

    ISSUE(0, 0); cpcommit();
    ISSUE(1, 1); cpcommit();

    for (int kt = 0; kt < 16; kt++) {              // 16 chunks of k=32
        cpwait<1>();
        __syncthreads();
        if (kt + 2 < 16) ISSUE(kt + 2, (kt + 2) % 3);
        cpcommit();

        const uint32_t* As  = sm + (kt % 3) * STW;
        const uint32_t* Bsm = As + 16 * AROW;
#pragma unroll
        for (int j = 0; j < 2; j++) {
            uint32_t afr[4][4], bfr[4][2];
#pragma unroll
            for (int mf = 0; mf < 4; mf++) {
                const int r0 = wm * 64 + mf * 16 + gq;
                afr[mf][0] = As[(8 * j + tq) * AROW + r0];
                afr[mf][1] = As[(8 * j + tq) * AROW + r0 + 8];
                afr[mf][2] = As[(8 * j + tq + 4) * AROW + r0];
                afr[mf][3] = As[(8 * j + tq + 4) * AROW + r0 + 8];
            }
#pragma unroll
            for (int nf = 0; nf < 4; nf++) {
                const int c0 = wn * 32 + nf * 8 + gq;
                bfr[nf][0] = Bsm[(8 * j + tq) * BROW + c0];
                bfr[nf][1] = Bsm[(8 * j + tq + 4) * BROW + c0];
            }
#pragma unroll
            for (int mf = 0; mf < 4; mf++)
#pragma unroll
                for (int nf = 0; nf < 4; nf++)
                    mma16(acc[mf][nf], afr[mf], bfr[nf]);
        }
    }

    const int n0 = bx * 128;
#pragma unroll
    for (int mf = 0; mf < 4; mf++)
#pragma unroll
        for (int nf = 0; nf < 4; nf++) {
            const int row = by * 128 + wm * 64 + mf * 16 + gq;   // = t*B_ + b
            const int col = n0 + wn * 32 + nf * 8 + tq * 2;
            const float b0v = bias[col], b1v = bias[col + 1];
            g_xph[(size_t)row * (G4_ / 2) + (col >> 1)] =
                __floats2half2_rn(acc[mf][nf][0] + b0v, acc[mf][nf][1] + b1v);
            g_xph[(size_t)(row + 8) * (G4_ / 2) + (col >> 1)] =
                __floats2half2_rn(acc[mf][nf][2] + b0v, acc[mf][nf][3] + b1v);
        }
}

// ---------------- stage 2: persistent fp16 recurrent kernel -----------------
// grid (16, 8) = 128 CTAs, 512 thr (16 warps, warp tile 32x32), 1 CTA/SM.
// U resident in smem; 4-stage A pipeline; xp prefetched during chunks 0-7;
// c in registers; hW staged -> coalesced 16B STG.
// Synchronization: per-producer progress flags. Chunk kt of step t reads h2
// rows [16kt,16kt+16) which are written solely by CTA (bx=kt, by) at the end
// of its step t-1 -> consumer spins on g_prog[by][kt] >= t right before the
// chunk's cp.async. No group-wide barrier; steps pipeline across CTAs.
__global__ void __launch_bounds__(512, 1)
lstm_rec(float* __restrict__ out)
{
    constexpr int AROW = 136;                     // mod 32 == 8
    constexpr int ASTW = 16 * AROW;               // 2176 words per A stage
    constexpr int NST  = 4;                       // pipeline stages
    constexpr int UOFF = NST * ASTW;              // 8704 words
    constexpr int XOFF = UOFF + 256 * 128;        // 41472 words
    constexpr int XR2  = 68;                      // xp row stride (half2 words)

    extern __shared__ __align__(16) uint32_t sm[];
    const uint32_t sbase = (uint32_t)__cvta_generic_to_shared(sm);
    const uint32_t* Us = sm + UOFF;
    const uint32_t* xp_sm = sm + XOFF;

    const int tid = threadIdx.x;
    const int bx = blockIdx.x, by = blockIdx.y;

    // ---- load U slice resident (256 k2-rows x 128 cols, rotation swizzle)
    {
#pragma unroll
        for (int i = 0; i < 16; i++) {
            const int q = tid + i * 512;
            const int row = q >> 5, m4 = (q & 31) * 4;
            const int gate = m4 >> 5, hid = m4 & 31;
            const uint32_t dst = (uint32_t)(UOFF + row * 128 + ((m4 + 8 * (row & 3)) & 127));
            cp16(sbase + dst * 4u, g_uh2 + (size_t)row * G4_ + gate * H_ + bx * 32 + hid);
        }
        cpcommit(); cpwait<0>();
        __syncthreads();
    }

    // ---- A (h) loader: 1 cp16/thread per chunk (16 k2 x 128 b = 8KB)
    const int ak2 = tid >> 5, am4 = (tid & 31) * 4;
    const uint32_t offA = (uint32_t)(ak2 * AROW + am4);
    const size_t   aoff = (size_t)ak2 * B_ + by * 128 + am4;

    // ---- xp loader: threads 0-255 do 1 cp16 per chunk for kt<8
    const int xrl = tid >> 4;                // 0..15 (valid when tid<256)
    const int xcc = tid & 15;
    const int xg  = xcc >> 2, xh2 = (xcc & 3) * 4;
    const uint32_t xdst0 = (uint32_t)(XOFF + xrl * XR2 + xg * 16 + xh2);
    const size_t   xsrc0 = ((size_t)(by * 128 + xrl)) * (G4_ / 2) + xg * (H_ / 2) + bx * 16 + xh2;

    const int warp = tid >> 5, lane = tid & 31;
    const int wm = warp >> 2, wn = warp & 3;     // 4x4 warp grid, tile 32x32
    const int gq = lane >> 2, tq = lane & 3;
    const int hidl = wn * 8 + tq * 2;
    const int hid2l = wn * 4 + tq;               // h2-row within the bx slice
    const int rotl = (wn * 8 + gq + 8 * tq);     // U swizzle: bank-free B frags

    float cst[2][2][2] = {};                     // cell state, registers only

    for (int t = 0; t < T_; t++) {
        const __half2* hbase = g_h2[t & 1];
        __half2*       hW    = g_h2[(t + 1) & 1];
        const __half2* xpg = g_xph + (size_t)t * B_ * (G4_ / 2);

        float acc[2][4][4] = {};

        auto WAITP = [&](int k) {
            unsigned v;
            do {
                asm volatile("ld.acquire.gpu.u32 %0, [%1];"
                             : "=r"(v) : "l"(&g_prog[by][k]) : "memory");
                if (v < (unsigned)t) __nanosleep(20);
            } while (v < (unsigned)t);
        };

        auto ISSUE = [&](int kt) {
            const uint32_t sb = sbase + (uint32_t)((kt & 3) * ASTW) * 4u;
            cp16(sb + offA * 4u, hbase + aoff + (size_t)kt * 16 * B_);
            if (kt < 8 && tid < 256)
                cp16(sbase + (xdst0 + (uint32_t)(16 * kt) * XR2) * 4u,
                     xpg + xsrc0 + (size_t)(16 * kt) * (G4_ / 2));
        };

        // ---- prime: wait for producers of chunks 0..2 (usually long done)
        if (tid == 0) { WAITP(0); WAITP(1); WAITP(2); }
        __syncthreads();
        ISSUE(0); cpcommit();
        ISSUE(1); cpcommit();
        ISSUE(2); cpcommit();

        for (int kt = 0; kt < 16; kt++) {
            cpwait<2>();
            if (tid == 0 && kt + 3 < 16) WAITP(kt + 3);
            __syncthreads();
            if (kt + 3 < 16) ISSUE(kt + 3);
            cpcommit();

            const uint32_t* As = sm + (kt & 3) * ASTW;
#pragma unroll
            for (int j = 0; j < 2; j++) {
                uint32_t afr[2][4], bfr[4][2];
#pragma unroll
                for (int mf = 0; mf < 2; mf++) {
                    const int r0 = wm * 32 + mf * 16 + gq;
                    afr[mf][0] = As[(8 * j + tq) * AROW + r0];
                    afr[mf][1] = As[(8 * j + tq) * AROW + r0 + 8];
                    afr[mf][2] = As[(8 * j + tq + 4) * AROW + r0];
                    afr[mf][3] = As[(8 * j + tq + 4) * AROW + r0 + 8];
                }
                const int ur0 = (kt * 16 + 8 * j + tq) * 128;
                const int ur1 = ur0 + 4 * 128;
#pragma unroll
                for (int nf = 0; nf < 4; nf++) {
                    const int cc = (nf * 32 + rotl) & 127;
                    bfr[nf][0] = Us[ur0 + cc];
                    bfr[nf][1] = Us[ur1 + cc];
                }
#pragma unroll
                for (int mf = 0; mf < 2; mf++)
#pragma unroll
                    for (int nf = 0; nf < 4; nf++)
                        mma16(acc[mf][nf], afr[mf], bfr[nf]);
            }
        }

        // ---- fused LSTM cell epilogue (xp from smem, c in registers)
        float2 outv[2][2];
#pragma unroll
        for (int mf = 0; mf < 2; mf++) {
#pragma unroll
            for (int rh = 0; rh < 2; rh++) {
                const int rl = wm * 32 + mf * 16 + rh * 8 + gq;   // local batch row
                float z[4][2];
#pragma unroll
                for (int g = 0; g < 4; g++) {
                    const float2 xv = __half22float2(
                        ((const __half2*)xp_sm)[rl * XR2 + g * 16 + (hidl >> 1)]);
                    z[g][0] = acc[mf][g][rh * 2 + 0] + xv.x;
                    z[g][1] = acc[mf][g][rh * 2 + 1] + xv.y;
                }
                float2 hh;
                {
                    const float ii = sigm(z[0][0]), ff = sigm(z[1][0]);
                    const float gg = tanh_(z[2][0]), oo = sigm(z[3][0]);
                    cst[mf][rh][0] = ff * cst[mf][rh][0] + ii * gg;
                    hh.x = oo * tanh_(cst[mf][rh][0]);
                }
                {
                    const float ii = sigm(z[0][1]), ff = sigm(z[1][1]);
                    const float gg = tanh_(z[2][1]), oo = sigm(z[3][1]);
                    cst[mf][rh][1] = ff * cst[mf][rh][1] + ii * gg;
                    hh.y = oo * tanh_(cst[mf][rh][1]);
                }
                outv[mf][rh] = hh;
                // stage half2 h into smem (stage-0 A region is free now)
                ((uint32_t*)sm)[hid2l * 136 + rl] = h2bits(hh.x, hh.y);
            }
        }
        __syncthreads();

        // ---- coalesced hW store: 16 k2-rows x 128 b (half2) = 8KB, 1 uint4/thr
        {
            const int row = tid >> 5, ch = tid & 31;
            const uint4 v = *(const uint4*)(sm + row * 136 + ch * 4);
            *(uint4*)(hW + (size_t)(bx * 16 + row) * B_ + by * 128 + ch * 4) = v;
        }
        __threadfence();
        __syncthreads();
        if (tid == 0) atomicAdd(&g_prog[by][bx], 1u);   // publish step t done

        // ---- out stores overlap the next step's waits (out is never read back)
#pragma unroll
        for (int mf = 0; mf < 2; mf++)
#pragma unroll
            for (int rh = 0; rh < 2; rh++) {
                const int rl = wm * 32 + mf * 16 + rh * 8 + gq;
                const int r = by * 128 + rl;
                *(float2*)&out[((size_t)r * T_ + t) * H_ + bx * 32 + hidl] = outv[mf][rh];
            }
    }
}

// ---------------- launch -----------------------------------------------------
extern "C" void kernel_launch(void* const* d_in, const int* in_sizes, int n_in,
                              void* d_out, int out_size)
{
    const float* X    = (const float*)d_in[0];   // [B, T, D]
    const float* W    = (const float*)d_in[1];   // [D, 4H]
    const float* U    = (const float*)d_in[2];   // [H, 4H]
    const float* bias = (const float*)d_in[3];   // [4H]
    float* out = (float*)d_out;                  // [B, T, H]

    constexpr int SM0 = 3 * (16 * 136 + 16 * 136) * 4;                  // 52224 B
    constexpr int SM1 = (4 * 16 * 136 + 256 * 128 + 128 * 68) * 4;      // 200704 B
    cudaFuncSetAttribute(gemm_x,   cudaFuncAttributeMaxDynamicSharedMemorySize, SM0);
    cudaFuncSetAttribute(lstm_rec, cudaFuncAttributeMaxDynamicSharedMemorySize, SM1);

    conv_wu<<<((D_ / 2) * G4_) / 256, 256>>>(W, U);
    prep_xh<<<dim3(D_ / 32, B_ / 32, T_), dim3(32, 8)>>>(X);
    zero_state<<<((H_ / 2) * B_) / 256, 256>>>();

    // Stage 1: input projection (128x128 tiles, fp16 operands, half2 output)
    gemm_x<<<dim3(G4_ / 128, (T_ * B_) / 128), 256, SM0>>>(bias);

    // Stage 2: single persistent kernel, 128 CTAs (1/SM, 16 warps), all 64 steps,
    // flag-synchronized (no group barrier)
    lstm_rec<<<dim3(16, 8), 512, SM1>>>(out);
}

// round 15
// speedup vs baseline: 1.1078x; 1.1078x over previous
#include <cuda_runtime.h>
#include <cuda_fp16.h>
#include <cstdint>

#define B_   1024
#define T_   64
#define D_   512
#define H_   512
#define G4_  2048   // 4*H

// ---------------- device scratch (no allocation allowed) --------------------
__device__ __half2 g_xph[(size_t)T_ * B_ * (G4_/2)];   // 256 MB: x@W + bias, [t][b][n2] half2
__device__ __half2 g_xh2[(size_t)T_ * (D_/2) * B_];    // 64 MB: X, [t][k2][b]
__device__ __half2 g_wh2[(size_t)(D_/2) * G4_];        // 2 MB: W, [k2][n]
__device__ __half2 g_uh2[(size_t)(H_/2) * G4_];        // 2 MB: U, [k2][n]
__device__ __half2 g_h2[2][(size_t)(H_/2) * B_];       // 2x1 MB: h, [k2][b], ping-pong
__device__ unsigned g_prog[8][16];                     // completed-step counter per (by, bx)

// ---------------- helpers ---------------------------------------------------
__device__ __forceinline__ void mma16(float* c, const uint32_t* a, const uint32_t* b) {
    asm volatile(
        "mma.sync.aligned.m16n8k16.row.col.f32.f16.f16.f32 "
        "{%0,%1,%2,%3}, {%4,%5,%6,%7}, {%8,%9}, {%0,%1,%2,%3};\n"
        : "+f"(c[0]), "+f"(c[1]), "+f"(c[2]), "+f"(c[3])
        : "r"(a[0]), "r"(a[1]), "r"(a[2]), "r"(a[3]),
          "r"(b[0]), "r"(b[1]));
}

__device__ __forceinline__ float sigm(float x) { return 1.0f / (1.0f + __expf(-x)); }
__device__ __forceinline__ float tanh_(float x) { return 1.0f - 2.0f / (__expf(2.0f * x) + 1.0f); }

__device__ __forceinline__ uint32_t h2bits(float a, float b) {
    __half2 h = __floats2half2_rn(a, b);
    return *reinterpret_cast<uint32_t*>(&h);
}

__device__ __forceinline__ void cp16(uint32_t s, const void* g) {
    asm volatile("cp.async.cg.shared.global [%0], [%1], 16;\n" :: "r"(s), "l"(g));
}
__device__ __forceinline__ void cpcommit() { asm volatile("cp.async.commit_group;\n"); }
template<int N> __device__ __forceinline__ void cpwait() {
    asm volatile("cp.async.wait_group %0;\n" :: "n"(N));
}

// ---------------- prep kernels ----------------------------------------------
__global__ void conv_wu(const float* __restrict__ W, const float* __restrict__ U) {
    const int i = blockIdx.x * blockDim.x + threadIdx.x;  // (D/2)*G4 = 512K
    const int n = i & (G4_ - 1), k2 = i >> 11;
    g_wh2[i] = __floats2half2_rn(W[(size_t)(2 * k2) * G4_ + n], W[(size_t)(2 * k2 + 1) * G4_ + n]);
    g_uh2[i] = __floats2half2_rn(U[(size_t)(2 * k2) * G4_ + n], U[(size_t)(2 * k2 + 1) * G4_ + n]);
}

// X[b][t][k] fp32 -> g_xh2[t][k2][b] half2
__global__ void prep_xh(const float* __restrict__ X) {
    __shared__ float tile[32][33];   // [b_local][k_local]
    const int t = blockIdx.z, k0 = blockIdx.x * 32, b0 = blockIdx.y * 32;
    const int tx = threadIdx.x, ty = threadIdx.y;
#pragma unroll
    for (int i = 0; i < 4; i++)
        tile[ty + i * 8][tx] = X[((size_t)(b0 + ty + i * 8) * T_ + t) * D_ + k0 + tx];
    __syncthreads();
#pragma unroll
    for (int i = 0; i < 2; i++) {
        const int k2 = ty + i * 8;   // 0..15
        g_xh2[((size_t)t * (D_ / 2) + (k0 >> 1) + k2) * B_ + b0 + tx] =
            __floats2half2_rn(tile[tx][2 * k2], tile[tx][2 * k2 + 1]);
    }
}

__global__ void zero_state() {
    const int i = blockIdx.x * blockDim.x + threadIdx.x;   // (H/2)*B = 262144
    const __half2 z = __floats2half2_rn(0.0f, 0.0f);
    g_h2[0][i] = z;
    g_h2[1][i] = z;
    if (i < 128) ((unsigned*)g_prog)[i] = 0u;
}

// ---------------- stage 1: fp16 pipelined GEMM (frozen) ---------------------
// XP = Xperm @ W + bias (-> half2), tiles 128x128, KC=32, grid (16,512), 2 CTA/SM
__global__ void __launch_bounds__(256, 2)
gemm_x(const float* __restrict__ bias)
{
    constexpr int AROW = 136, BROW = 136;          // mod 32 == 8 -> conflict-free
    constexpr int STW  = 16 * AROW + 16 * BROW;    // 4352 words per stage

    extern __shared__ __align__(16) uint32_t sm[];
    const uint32_t sbase = (uint32_t)__cvta_generic_to_shared(sm);

    const int tid = threadIdx.x;
    const int bx = blockIdx.x, by = blockIdx.y;

    const int tt = by >> 3, m0 = (by & 7) * 128;
    const __half2* Ab = g_xh2 + (size_t)tt * (D_ / 2) * B_ + m0;

    uint32_t offA[2], offB[2];
    const __half2* aG[2];
    const __half2* bG[2];
#pragma unroll
    for (int c = 0; c < 2; c++) {
        const int q = tid + c * 256;
        const int k2 = q >> 5, m4 = (q & 31) * 4;
        offA[c] = (uint32_t)(k2 * AROW + m4);
        aG[c]   = Ab + (size_t)k2 * B_ + m4;
        offB[c] = (uint32_t)(16 * AROW + k2 * BROW + m4);
        bG[c]   = g_wh2 + (size_t)k2 * G4_ + bx * 128 + m4;
    }

    const int warp = tid >> 5, lane = tid & 31;
    const int wm = warp >> 2, wn = warp & 3;
    const int gq = lane >> 2, tq = lane & 3;

    float acc[4][4][4] = {};

    auto ISSUE = [&](int kt, int s) {
#pragma unroll
        for (int c = 0; c < 2; c++) {
            cp16(sbase + (uint32_t)(s * STW + offA[c]) * 4u, aG[c] + (size_t)kt * 16 * B_);
            cp16(sbase + (uint32_t)(s * STW + offB[c]) * 4u, bG[c] + (size_t)kt * 16 * G4_);
        }
    };

    ISSUE(0, 0); cpcommit();
    ISSUE(1, 1); cpcommit();

    for (int kt = 0; kt < 16; kt++) {              // 16 chunks of k=32
        cpwait<1>();
        __syncthreads();
        if (kt + 2 < 16) ISSUE(kt + 2, (kt + 2) % 3);
        cpcommit();

        const uint32_t* As  = sm + (kt % 3) * STW;
        const uint32_t* Bsm = As + 16 * AROW;
#pragma unroll
        for (int j = 0; j < 2; j++) {
            uint32_t afr[4][4], bfr[4][2];
#pragma unroll
            for (int mf = 0; mf < 4; mf++) {
                const int r0 = wm * 64 + mf * 16 + gq;
                afr[mf][0] = As[(8 * j + tq) * AROW + r0];
                afr[mf][1] = As[(8 * j + tq) * AROW + r0 + 8];
                afr[mf][2] = As[(8 * j + tq + 4) * AROW + r0];
                afr[mf][3] = As[(8 * j + tq + 4) * AROW + r0 + 8];
            }
#pragma unroll
            for (int nf = 0; nf < 4; nf++) {
                const int c0 = wn * 32 + nf * 8 + gq;
                bfr[nf][0] = Bsm[(8 * j + tq) * BROW + c0];
                bfr[nf][1] = Bsm[(8 * j + tq + 4) * BROW + c0];
            }
#pragma unroll
            for (int mf = 0; mf < 4; mf++)
#pragma unroll
                for (int nf = 0; nf < 4; nf++)
                    mma16(acc[mf][nf], afr[mf], bfr[nf]);
        }
    }

    const int n0 = bx * 128;
#pragma unroll
    for (int mf = 0; mf < 4; mf++)
#pragma unroll
        for (int nf = 0; nf < 4; nf++) {
            const int row = by * 128 + wm * 64 + mf * 16 + gq;   // = t*B_ + b
            const int col = n0 + wn * 32 + nf * 8 + tq * 2;
            const float b0v = bias[col], b1v = bias[col + 1];
            g_xph[(size_t)row * (G4_ / 2) + (col >> 1)] =
                __floats2half2_rn(acc[mf][nf][0] + b0v, acc[mf][nf][1] + b1v);
            g_xph[(size_t)(row + 8) * (G4_ / 2) + (col >> 1)] =
                __floats2half2_rn(acc[mf][nf][2] + b0v, acc[mf][nf][3] + b1v);
        }
}

// ---------------- stage 2: persistent fp16 recurrent kernel -----------------
// grid (16, 8) = 128 CTAs, 512 thr (16 warps, warp tile 32x32), 1 CTA/SM.
// U resident in smem; 4-stage A pipeline; xp prefetched during chunks 0-7;
// c in registers; hW staged -> coalesced 16B STG.
// Sync: per-producer progress flags, BATCHED PARALLEL waits (3 phases/step):
//   step start: threads 0-7 poll flags 0-7   (chunks 0-7 issued kt=-3..4)
//   kt==4:      threads 8-11 poll flags 8-11 (chunk 8 issued at kt=5)
//   kt==8:      threads 12-15 poll flags 12-15 (chunk 12 issued at kt=9)
// Publishing step t requires having READ all of H[t] (full-K), so the
// 2-buffer ping-pong WAR is covered by the flag order (proven safe).
__global__ void __launch_bounds__(512, 1)
lstm_rec(float* __restrict__ out)
{
    constexpr int AROW = 136;                     // mod 32 == 8
    constexpr int ASTW = 16 * AROW;               // 2176 words per A stage
    constexpr int NST  = 4;                       // pipeline stages
    constexpr int UOFF = NST * ASTW;              // 8704 words
    constexpr int XOFF = UOFF + 256 * 128;        // 41472 words
    constexpr int XR2  = 68;                      // xp row stride (half2 words)

    extern __shared__ __align__(16) uint32_t sm[];
    const uint32_t sbase = (uint32_t)__cvta_generic_to_shared(sm);
    const uint32_t* Us = sm + UOFF;
    const uint32_t* xp_sm = sm + XOFF;

    const int tid = threadIdx.x;
    const int bx = blockIdx.x, by = blockIdx.y;

    // ---- load U slice resident (256 k2-rows x 128 cols, rotation swizzle)
    {
#pragma unroll
        for (int i = 0; i < 16; i++) {
            const int q = tid + i * 512;
            const int row = q >> 5, m4 = (q & 31) * 4;
            const int gate = m4 >> 5, hid = m4 & 31;
            const uint32_t dst = (uint32_t)(UOFF + row * 128 + ((m4 + 8 * (row & 3)) & 127));
            cp16(sbase + dst * 4u, g_uh2 + (size_t)row * G4_ + gate * H_ + bx * 32 + hid);
        }
        cpcommit(); cpwait<0>();
        __syncthreads();
    }

    // ---- A (h) loader: 1 cp16/thread per chunk (16 k2 x 128 b = 8KB)
    const int ak2 = tid >> 5, am4 = (tid & 31) * 4;
    const uint32_t offA = (uint32_t)(ak2 * AROW + am4);
    const size_t   aoff = (size_t)ak2 * B_ + by * 128 + am4;

    // ---- xp loader: threads 0-255 do 1 cp16 per chunk for kt<8
    const int xrl = tid >> 4;                // 0..15 (valid when tid<256)
    const int xcc = tid & 15;
    const int xg  = xcc >> 2, xh2 = (xcc & 3) * 4;
    const uint32_t xdst0 = (uint32_t)(XOFF + xrl * XR2 + xg * 16 + xh2);
    const size_t   xsrc0 = ((size_t)(by * 128 + xrl)) * (G4_ / 2) + xg * (H_ / 2) + bx * 16 + xh2;

    const int warp = tid >> 5, lane = tid & 31;
    const int wm = warp >> 2, wn = warp & 3;     // 4x4 warp grid, tile 32x32
    const int gq = lane >> 2, tq = lane & 3;
    const int hidl = wn * 8 + tq * 2;
    const int hid2l = wn * 4 + tq;               // h2-row within the bx slice
    const int rotl = (wn * 8 + gq + 8 * tq);     // U swizzle: bank-free B frags

    float cst[2][2][2] = {};                     // cell state, registers only

    for (int t = 0; t < T_; t++) {
        const __half2* hbase = g_h2[t & 1];
        __half2*       hW    = g_h2[(t + 1) & 1];
        const __half2* xpg = g_xph + (size_t)t * B_ * (G4_ / 2);

        float acc[2][4][4] = {};

        auto WAITP = [&](int k) {
            unsigned v;
            do {
                asm volatile("ld.acquire.gpu.u32 %0, [%1];"
                             : "=r"(v) : "l"(&g_prog[by][k]) : "memory");
                if (v < (unsigned)t) __nanosleep(20);
            } while (v < (unsigned)t);
        };

        auto ISSUE = [&](int kt) {
            const uint32_t sb = sbase + (uint32_t)((kt & 3) * ASTW) * 4u;
            cp16(sb + offA * 4u, hbase + aoff + (size_t)kt * 16 * B_);
            if (kt < 8 && tid < 256)
                cp16(sbase + (xdst0 + (uint32_t)(16 * kt) * XR2) * 4u,
                     xpg + xsrc0 + (size_t)(16 * kt) * (G4_ / 2));
        };

        // ---- phase 1: parallel wait for producers of chunks 0..7
        if (tid < 8) WAITP(tid);
        __syncthreads();
        ISSUE(0); cpcommit();
        ISSUE(1); cpcommit();
        ISSUE(2); cpcommit();

        for (int kt = 0; kt < 16; kt++) {
            cpwait<2>();
            // phases 2/3: parallel waits for later producers, batched
            if (kt == 4 && tid >= 8 && tid < 12) WAITP(tid);
            if (kt == 8 && tid >= 12 && tid < 16) WAITP(tid);
            __syncthreads();
            if (kt + 3 < 16) ISSUE(kt + 3);
            cpcommit();

            const uint32_t* As = sm + (kt & 3) * ASTW;
#pragma unroll
            for (int j = 0; j < 2; j++) {
                uint32_t afr[2][4], bfr[4][2];
#pragma unroll
                for (int mf = 0; mf < 2; mf++) {
                    const int r0 = wm * 32 + mf * 16 + gq;
                    afr[mf][0] = As[(8 * j + tq) * AROW + r0];
                    afr[mf][1] = As[(8 * j + tq) * AROW + r0 + 8];
                    afr[mf][2] = As[(8 * j + tq + 4) * AROW + r0];
                    afr[mf][3] = As[(8 * j + tq + 4) * AROW + r0 + 8];
                }
                const int ur0 = (kt * 16 + 8 * j + tq) * 128;
                const int ur1 = ur0 + 4 * 128;
#pragma unroll
                for (int nf = 0; nf < 4; nf++) {
                    const int cc = (nf * 32 + rotl) & 127;
                    bfr[nf][0] = Us[ur0 + cc];
                    bfr[nf][1] = Us[ur1 + cc];
                }
#pragma unroll
                for (int mf = 0; mf < 2; mf++)
#pragma unroll
                    for (int nf = 0; nf < 4; nf++)
                        mma16(acc[mf][nf], afr[mf], bfr[nf]);
            }
        }

        // ---- fused LSTM cell epilogue (xp from smem, c in registers)
        float2 outv[2][2];
#pragma unroll
        for (int mf = 0; mf < 2; mf++) {
#pragma unroll
            for (int rh = 0; rh < 2; rh++) {
                const int rl = wm * 32 + mf * 16 + rh * 8 + gq;   // local batch row
                float z[4][2];
#pragma unroll
                for (int g = 0; g < 4; g++) {
                    const float2 xv = __half22float2(
                        ((const __half2*)xp_sm)[rl * XR2 + g * 16 + (hidl >> 1)]);
                    z[g][0] = acc[mf][g][rh * 2 + 0] + xv.x;
                    z[g][1] = acc[mf][g][rh * 2 + 1] + xv.y;
                }
                float2 hh;
                {
                    const float ii = sigm(z[0][0]), ff = sigm(z[1][0]);
                    const float gg = tanh_(z[2][0]), oo = sigm(z[3][0]);
                    cst[mf][rh][0] = ff * cst[mf][rh][0] + ii * gg;
                    hh.x = oo * tanh_(cst[mf][rh][0]);
                }
                {
                    const float ii = sigm(z[0][1]), ff = sigm(z[1][1]);
                    const float gg = tanh_(z[2][1]), oo = sigm(z[3][1]);
                    cst[mf][rh][1] = ff * cst[mf][rh][1] + ii * gg;
                    hh.y = oo * tanh_(cst[mf][rh][1]);
                }
                outv[mf][rh] = hh;
                // stage half2 h into smem (stage-0 A region is free now)
                ((uint32_t*)sm)[hid2l * 136 + rl] = h2bits(hh.x, hh.y);
            }
        }
        __syncthreads();

        // ---- coalesced hW store: 16 k2-rows x 128 b (half2) = 8KB, 1 uint4/thr
        {
            const int row = tid >> 5, ch = tid & 31;
            const uint4 v = *(const uint4*)(sm + row * 136 + ch * 4);
            *(uint4*)(hW + (size_t)(bx * 16 + row) * B_ + by * 128 + ch * 4) = v;
        }
        __threadfence();
        __syncthreads();
        if (tid == 0) atomicAdd(&g_prog[by][bx], 1u);   // publish step t done

        // ---- out stores overlap the next step's waits (out is never read back)
#pragma unroll
        for (int mf = 0; mf < 2; mf++)
#pragma unroll
            for (int rh = 0; rh < 2; rh++) {
                const int rl = wm * 32 + mf * 16 + rh * 8 + gq;
                const int r = by * 128 + rl;
                *(float2*)&out[((size_t)r * T_ + t) * H_ + bx * 32 + hidl] = outv[mf][rh];
            }
    }
}

// ---------------- launch -----------------------------------------------------
extern "C" void kernel_launch(void* const* d_in, const int* in_sizes, int n_in,
                              void* d_out, int out_size)
{
    const float* X    = (const float*)d_in[0];   // [B, T, D]
    const float* W    = (const float*)d_in[1];   // [D, 4H]
    const float* U    = (const float*)d_in[2];   // [H, 4H]
    const float* bias = (const float*)d_in[3];   // [4H]
    float* out = (float*)d_out;                  // [B, T, H]

    constexpr int SM0 = 3 * (16 * 136 + 16 * 136) * 4;                  // 52224 B
    constexpr int SM1 = (4 * 16 * 136 + 256 * 128 + 128 * 68) * 4;      // 200704 B
    cudaFuncSetAttribute(gemm_x,   cudaFuncAttributeMaxDynamicSharedMemorySize, SM0);
    cudaFuncSetAttribute(lstm_rec, cudaFuncAttributeMaxDynamicSharedMemorySize, SM1);

    conv_wu<<<((D_ / 2) * G4_) / 256, 256>>>(W, U);
    prep_xh<<<dim3(D_ / 32, B_ / 32, T_), dim3(32, 8)>>>(X);
    zero_state<<<((H_ / 2) * B_) / 256, 256>>>();

    // Stage 1: input projection (128x128 tiles, fp16 operands, half2 output)
    gemm_x<<<dim3(G4_ / 128, (T_ * B_) / 128), 256, SM0>>>(bias);

    // Stage 2: single persistent kernel, 128 CTAs (1/SM, 16 warps), all 64 steps,
    // flag-synchronized with batched parallel waits
    lstm_rec<<<dim3(16, 8), 512, SM1>>>(out);
}

// round 16
// speedup vs baseline: 1.1929x; 1.0769x over previous
#include <cuda_runtime.h>
#include <cuda_fp16.h>
#include <cstdint>

#define B_   1024
#define T_   64
#define D_   512
#define H_   512
#define G4_  2048   // 4*H

// ---------------- device scratch (no allocation allowed) --------------------
__device__ __half2 g_xph[(size_t)T_ * B_ * (G4_/2)];   // 256 MB: x@W + bias, [t][b][n2] half2
__device__ __half2 g_xh2[(size_t)T_ * (D_/2) * B_];    // 64 MB: X, [t][k2][b]
__device__ __half2 g_wh2[(size_t)(D_/2) * G4_];        // 2 MB: W, [k2][n]
__device__ __half2 g_uh2[(size_t)(H_/2) * G4_];        // 2 MB: U, [k2][n]
__device__ __half2 g_h2[2][(size_t)(H_/2) * B_];       // 2x1 MB: h, [k2][b], ping-pong
__device__ unsigned g_bar[8];                          // per-by-group step barriers

// ---------------- helpers ---------------------------------------------------
__device__ __forceinline__ void mma16(float* c, const uint32_t* a, const uint32_t* b) {
    asm volatile(
        "mma.sync.aligned.m16n8k16.row.col.f32.f16.f16.f32 "
        "{%0,%1,%2,%3}, {%4,%5,%6,%7}, {%8,%9}, {%0,%1,%2,%3};\n"
        : "+f"(c[0]), "+f"(c[1]), "+f"(c[2]), "+f"(c[3])
        : "r"(a[0]), "r"(a[1]), "r"(a[2]), "r"(a[3]),
          "r"(b[0]), "r"(b[1]));
}

__device__ __forceinline__ float sigm(float x) { return 1.0f / (1.0f + __expf(-x)); }
__device__ __forceinline__ float tanh_(float x) { return 1.0f - 2.0f / (__expf(2.0f * x) + 1.0f); }

__device__ __forceinline__ uint32_t h2bits(float a, float b) {
    __half2 h = __floats2half2_rn(a, b);
    return *reinterpret_cast<uint32_t*>(&h);
}

__device__ __forceinline__ void cp16(uint32_t s, const void* g) {
    asm volatile("cp.async.cg.shared.global [%0], [%1], 16;\n" :: "r"(s), "l"(g));
}
__device__ __forceinline__ void cpcommit() { asm volatile("cp.async.commit_group;\n"); }
template<int N> __device__ __forceinline__ void cpwait() {
    asm volatile("cp.async.wait_group %0;\n" :: "n"(N));
}

// ---------------- prep kernels ----------------------------------------------
__global__ void conv_wu(const float* __restrict__ W, const float* __restrict__ U) {
    const int i = blockIdx.x * blockDim.x + threadIdx.x;  // (D/2)*G4 = 512K
    const int n = i & (G4_ - 1), k2 = i >> 11;
    g_wh2[i] = __floats2half2_rn(W[(size_t)(2 * k2) * G4_ + n], W[(size_t)(2 * k2 + 1) * G4_ + n]);
    g_uh2[i] = __floats2half2_rn(U[(size_t)(2 * k2) * G4_ + n], U[(size_t)(2 * k2 + 1) * G4_ + n]);
}

// X[b][t][k] fp32 -> g_xh2[t][k2][b] half2
__global__ void prep_xh(const float* __restrict__ X) {
    __shared__ float tile[32][33];   // [b_local][k_local]
    const int t = blockIdx.z, k0 = blockIdx.x * 32, b0 = blockIdx.y * 32;
    const int tx = threadIdx.x, ty = threadIdx.y;
#pragma unroll
    for (int i = 0; i < 4; i++)
        tile[ty + i * 8][tx] = X[((size_t)(b0 + ty + i * 8) * T_ + t) * D_ + k0 + tx];
    __syncthreads();
#pragma unroll
    for (int i = 0; i < 2; i++) {
        const int k2 = ty + i * 8;   // 0..15
        g_xh2[((size_t)t * (D_ / 2) + (k0 >> 1) + k2) * B_ + b0 + tx] =
            __floats2half2_rn(tile[tx][2 * k2], tile[tx][2 * k2 + 1]);
    }
}

__global__ void zero_state() {
    const int i = blockIdx.x * blockDim.x + threadIdx.x;   // (H/2)*B = 262144
    const __half2 z = __floats2half2_rn(0.0f, 0.0f);
    g_h2[0][i] = z;
    g_h2[1][i] = z;
    if (i < 8) g_bar[i] = 0u;
}

// ---------------- stage 1: fp16 pipelined GEMM, KC=64 -----------------------
// XP = Xperm @ W + bias (-> half2), tiles 128x128, 8 chunks of k=64,
// grid (16,512), 256 thr, 2 CTA/SM
__global__ void __launch_bounds__(256, 2)
gemm_x(const float* __restrict__ bias)
{
    constexpr int AROW = 136, BROW = 136;          // mod 32 == 8 -> conflict-free
    constexpr int STW  = 32 * AROW + 32 * BROW;    // 8704 words per stage

    extern __shared__ __align__(16) uint32_t sm[];
    const uint32_t sbase = (uint32_t)__cvta_generic_to_shared(sm);

    const int tid = threadIdx.x;
    const int bx = blockIdx.x, by = blockIdx.y;

    const int tt = by >> 3, m0 = (by & 7) * 128;
    const __half2* Ab = g_xh2 + (size_t)tt * (D_ / 2) * B_ + m0;

    uint32_t offA[4], offB[4];
    const __half2* aG[4];
    const __half2* bG[4];
#pragma unroll
    for (int c = 0; c < 4; c++) {
        const int q = tid + c * 256;
        const int k2 = q >> 5, m4 = (q & 31) * 4;   // k2 0..31
        offA[c] = (uint32_t)(k2 * AROW + m4);
        aG[c]   = Ab + (size_t)k2 * B_ + m4;
        offB[c] = (uint32_t)(32 * AROW + k2 * BROW + m4);
        bG[c]   = g_wh2 + (size_t)k2 * G4_ + bx * 128 + m4;
    }

    const int warp = tid >> 5, lane = tid & 31;
    const int wm = warp >> 2, wn = warp & 3;
    const int gq = lane >> 2, tq = lane & 3;

    float acc[4][4][4] = {};

    auto ISSUE = [&](int kt, int s) {
#pragma unroll
        for (int c = 0; c < 4; c++) {
            cp16(sbase + (uint32_t)(s * STW + offA[c]) * 4u, aG[c] + (size_t)kt * 32 * B_);
            cp16(sbase + (uint32_t)(s * STW + offB[c]) * 4u, bG[c] + (size_t)kt * 32 * G4_);
        }
    };

    ISSUE(0, 0); cpcommit();
    ISSUE(1, 1); cpcommit();

    for (int kt = 0; kt < 8; kt++) {               // 8 chunks of k=64
        cpwait<1>();
        __syncthreads();
        if (kt + 2 < 8) ISSUE(kt + 2, (kt + 2) % 3);
        cpcommit();

        const uint32_t* As  = sm + (kt % 3) * STW;
        const uint32_t* Bsm = As + 32 * AROW;
#pragma unroll
        for (int j = 0; j < 4; j++) {              // four k16 mma groups
            uint32_t afr[4][4], bfr[4][2];
#pragma unroll
            for (int mf = 0; mf < 4; mf++) {
                const int r0 = wm * 64 + mf * 16 + gq;
                afr[mf][0] = As[(8 * j + tq) * AROW + r0];
                afr[mf][1] = As[(8 * j + tq) * AROW + r0 + 8];
                afr[mf][2] = As[(8 * j + tq + 4) * AROW + r0];
                afr[mf][3] = As[(8 * j + tq + 4) * AROW + r0 + 8];
            }
#pragma unroll
            for (int nf = 0; nf < 4; nf++) {
                const int c0 = wn * 32 + nf * 8 + gq;
                bfr[nf][0] = Bsm[(8 * j + tq) * BROW + c0];
                bfr[nf][1] = Bsm[(8 * j + tq + 4) * BROW + c0];
            }
#pragma unroll
            for (int mf = 0; mf < 4; mf++)
#pragma unroll
                for (int nf = 0; nf < 4; nf++)
                    mma16(acc[mf][nf], afr[mf], bfr[nf]);
        }
    }

    const int n0 = bx * 128;
#pragma unroll
    for (int mf = 0; mf < 4; mf++)
#pragma unroll
        for (int nf = 0; nf < 4; nf++) {
            const int row = by * 128 + wm * 64 + mf * 16 + gq;   // = t*B_ + b
            const int col = n0 + wn * 32 + nf * 8 + tq * 2;
            const float b0v = bias[col], b1v = bias[col + 1];
            g_xph[(size_t)row * (G4_ / 2) + (col >> 1)] =
                __floats2half2_rn(acc[mf][nf][0] + b0v, acc[mf][nf][1] + b1v);
            g_xph[(size_t)(row + 8) * (G4_ / 2) + (col >> 1)] =
                __floats2half2_rn(acc[mf][nf][2] + b0v, acc[mf][nf][3] + b1v);
        }
}

// ---------------- stage 2: persistent fp16 recurrent kernel, KC=64 ----------
// grid (16, 8) = 128 CTAs, 512 thr (16 warps, warp tile 32x32), 1 CTA/SM.
// U resident in smem; 3-stage A pipeline of k=64 chunks (8 chunks/step);
// xp prefetched during chunks 0-3; c in registers; hW staged -> 16B STG;
// per-by-group (16 CTA) spin barrier between steps (proven fastest sync).
__global__ void __launch_bounds__(512, 1)
lstm_rec(float* __restrict__ out)
{
    constexpr int AROW = 136;                     // mod 32 == 8
    constexpr int ASTW = 32 * AROW;               // 4352 words per A stage
    constexpr int NST  = 3;                       // pipeline stages
    constexpr int UOFF = NST * ASTW;              // 13056 words
    constexpr int XOFF = UOFF + 256 * 128;        // 45824 words
    constexpr int XR2  = 68;                      // xp row stride (half2 words)

    extern __shared__ __align__(16) uint32_t sm[];
    const uint32_t sbase = (uint32_t)__cvta_generic_to_shared(sm);
    const uint32_t* Us = sm + UOFF;
    const uint32_t* xp_sm = sm + XOFF;

    const int tid = threadIdx.x;
    const int bx = blockIdx.x, by = blockIdx.y;

    // ---- load U slice resident (256 k2-rows x 128 cols, rotation swizzle)
    {
#pragma unroll
        for (int i = 0; i < 16; i++) {
            const int q = tid + i * 512;
            const int row = q >> 5, m4 = (q & 31) * 4;
            const int gate = m4 >> 5, hid = m4 & 31;
            const uint32_t dst = (uint32_t)(UOFF + row * 128 + ((m4 + 8 * (row & 3)) & 127));
            cp16(sbase + dst * 4u, g_uh2 + (size_t)row * G4_ + gate * H_ + bx * 32 + hid);
        }
        cpcommit(); cpwait<0>();
        __syncthreads();
    }

    // ---- A (h) loader: 2 cp16/thread per chunk (32 k2 x 128 b = 16KB)
    uint32_t offA[2];
    size_t aoff[2];
#pragma unroll
    for (int c = 0; c < 2; c++) {
        const int q = tid + c * 512;
        const int k2 = q >> 5, m4 = (q & 31) * 4;   // k2 0..31
        offA[c] = (uint32_t)(k2 * AROW + m4);
        aoff[c] = (size_t)k2 * B_ + by * 128 + m4;
    }

    // ---- xp loader: all 512 thr, 1 cp16 per chunk for kt<4 (32 rows/chunk)
    const int xrl = tid >> 4;                // 0..31
    const int xcc = tid & 15;
    const int xg  = xcc >> 2, xh2 = (xcc & 3) * 4;
    const uint32_t xdst0 = (uint32_t)(XOFF + xrl * XR2 + xg * 16 + xh2);
    const size_t   xsrc0 = ((size_t)(by * 128 + xrl)) * (G4_ / 2) + xg * (H_ / 2) + bx * 16 + xh2;

    const int warp = tid >> 5, lane = tid & 31;
    const int wm = warp >> 2, wn = warp & 3;     // 4x4 warp grid, tile 32x32
    const int gq = lane >> 2, tq = lane & 3;
    const int hidl = wn * 8 + tq * 2;
    const int hid2l = wn * 4 + tq;               // h2-row within the bx slice
    const int rotl = (wn * 8 + gq + 8 * tq);     // U swizzle: bank-free B frags

    float cst[2][2][2] = {};                     // cell state, registers only

    for (int t = 0; t < T_; t++) {
        const __half2* hbase = g_h2[t & 1];
        __half2*       hW    = g_h2[(t + 1) & 1];
        const __half2* xpg = g_xph + (size_t)t * B_ * (G4_ / 2);

        float acc[2][4][4] = {};

        auto ISSUE = [&](int kt) {
            const uint32_t sb = sbase + (uint32_t)((kt % 3) * ASTW) * 4u;
#pragma unroll
            for (int c = 0; c < 2; c++)
                cp16(sb + offA[c] * 4u, hbase + aoff[c] + (size_t)kt * 32 * B_);
            if (kt < 4)
                cp16(sbase + (xdst0 + (uint32_t)(32 * kt) * XR2) * 4u,
                     xpg + xsrc0 + (size_t)(32 * kt) * (G4_ / 2));
        };

        ISSUE(0); cpcommit();
        ISSUE(1); cpcommit();

        for (int kt = 0; kt < 8; kt++) {           // 8 chunks of k=64
            cpwait<1>();
            __syncthreads();
            if (kt + 2 < 8) ISSUE(kt + 2);
            cpcommit();

            const uint32_t* As = sm + (kt % 3) * ASTW;
#pragma unroll
            for (int j = 0; j < 4; j++) {
                uint32_t afr[2][4], bfr[4][2];
#pragma unroll
                for (int mf = 0; mf < 2; mf++) {
                    const int r0 = wm * 32 + mf * 16 + gq;
                    afr[mf][0] = As[(8 * j + tq) * AROW + r0];
                    afr[mf][1] = As[(8 * j + tq) * AROW + r0 + 8];
                    afr[mf][2] = As[(8 * j + tq + 4) * AROW + r0];
                    afr[mf][3] = As[(8 * j + tq + 4) * AROW + r0 + 8];
                }
                const int ur0 = (kt * 32 + 8 * j + tq) * 128;
                const int ur1 = ur0 + 4 * 128;
#pragma unroll
                for (int nf = 0; nf < 4; nf++) {
                    const int cc = (nf * 32 + rotl) & 127;
                    bfr[nf][0] = Us[ur0 + cc];
                    bfr[nf][1] = Us[ur1 + cc];
                }
#pragma unroll
                for (int mf = 0; mf < 2; mf++)
#pragma unroll
                    for (int nf = 0; nf < 4; nf++)
                        mma16(acc[mf][nf], afr[mf], bfr[nf]);
            }
        }

        // ---- fused LSTM cell epilogue (xp from smem, c in registers)
        float2 outv[2][2];
#pragma unroll
        for (int mf = 0; mf < 2; mf++) {
#pragma unroll
            for (int rh = 0; rh < 2; rh++) {
                const int rl = wm * 32 + mf * 16 + rh * 8 + gq;   // local batch row
                float z[4][2];
#pragma unroll
                for (int g = 0; g < 4; g++) {
                    const float2 xv = __half22float2(
                        ((const __half2*)xp_sm)[rl * XR2 + g * 16 + (hidl >> 1)]);
                    z[g][0] = acc[mf][g][rh * 2 + 0] + xv.x;
                    z[g][1] = acc[mf][g][rh * 2 + 1] + xv.y;
                }
                float2 hh;
                {
                    const float ii = sigm(z[0][0]), ff = sigm(z[1][0]);
                    const float gg = tanh_(z[2][0]), oo = sigm(z[3][0]);
                    cst[mf][rh][0] = ff * cst[mf][rh][0] + ii * gg;
                    hh.x = oo * tanh_(cst[mf][rh][0]);
                }
                {
                    const float ii = sigm(z[0][1]), ff = sigm(z[1][1]);
                    const float gg = tanh_(z[2][1]), oo = sigm(z[3][1]);
                    cst[mf][rh][1] = ff * cst[mf][rh][1] + ii * gg;
                    hh.y = oo * tanh_(cst[mf][rh][1]);
                }
                outv[mf][rh] = hh;
                // stage half2 h into smem (stage-0 A region: last read was chunk 6)
                ((uint32_t*)sm)[hid2l * 136 + rl] = h2bits(hh.x, hh.y);
            }
        }
        __syncthreads();

        // ---- coalesced hW store: 16 k2-rows x 128 b (half2) = 8KB, 1 uint4/thr
        {
            const int row = tid >> 5, ch = tid & 31;
            const uint4 v = *(const uint4*)(sm + row * 136 + ch * 4);
            *(uint4*)(hW + (size_t)(bx * 16 + row) * B_ + by * 128 + ch * 4) = v;
        }
        __threadfence();
        __syncthreads();
        if (tid == 0) atomicAdd(&g_bar[by], 1u);

        // ---- out stores overlap the barrier wait (out is never read back)
#pragma unroll
        for (int mf = 0; mf < 2; mf++)
#pragma unroll
            for (int rh = 0; rh < 2; rh++) {
                const int rl = wm * 32 + mf * 16 + rh * 8 + gq;
                const int r = by * 128 + rl;
                *(float2*)&out[((size_t)r * T_ + t) * H_ + bx * 32 + hidl] = outv[mf][rh];
            }

        if (tid == 0) {
            const unsigned tgt = 16u * (unsigned)(t + 1);
            unsigned v;
            do {
                asm volatile("ld.acquire.gpu.u32 %0, [%1];"
                             : "=r"(v) : "l"(&g_bar[by]) : "memory");
                if (v < tgt) __nanosleep(20);
            } while (v < tgt);
        }
        __syncthreads();
    }
}

// ---------------- launch -----------------------------------------------------
extern "C" void kernel_launch(void* const* d_in, const int* in_sizes, int n_in,
                              void* d_out, int out_size)
{
    const float* X    = (const float*)d_in[0];   // [B, T, D]
    const float* W    = (const float*)d_in[1];   // [D, 4H]
    const float* U    = (const float*)d_in[2];   // [H, 4H]
    const float* bias = (const float*)d_in[3];   // [4H]
    float* out = (float*)d_out;                  // [B, T, H]

    constexpr int SM0 = 3 * (32 * 136 + 32 * 136) * 4;                  // 104448 B
    constexpr int SM1 = (3 * 32 * 136 + 256 * 128 + 128 * 68) * 4;      // 218112 B
    cudaFuncSetAttribute(gemm_x,   cudaFuncAttributeMaxDynamicSharedMemorySize, SM0);
    cudaFuncSetAttribute(lstm_rec, cudaFuncAttributeMaxDynamicSharedMemorySize, SM1);

    conv_wu<<<((D_ / 2) * G4_) / 256, 256>>>(W, U);
    prep_xh<<<dim3(D_ / 32, B_ / 32, T_), dim3(32, 8)>>>(X);
    zero_state<<<((H_ / 2) * B_) / 256, 256>>>();

    // Stage 1: input projection (128x128 tiles, fp16 operands, half2 output)
    gemm_x<<<dim3(G4_ / 128, (T_ * B_) / 128), 256, SM0>>>(bias);

    // Stage 2: single persistent kernel, 128 CTAs (1/SM, 16 warps), all 64 steps
    lstm_rec<<<dim3(16, 8), 512, SM1>>>(out);
}